// round 2
// baseline (speedup 1.0000x reference)
#include <cuda_runtime.h>
#include <cuda_bf16.h>
#include <mma.h>

using namespace nvcuda;

#define MAX_NODES 100000
#define HID 128

// Scratch: precomputed per-node projections (fp32 this round; bf16 candidate later)
__device__ float g_U[(size_t)MAX_NODES * HID];   // Z @ W1[0:128,:]
__device__ float g_V[(size_t)MAX_NODES * HID];   // Z @ W1[128:256,:]

extern __shared__ float s_B[];   // [128 k][256 n] combined, tf32-rounded

// ---------------------------------------------------------------------------
// Precompute kernel: one block = 64 node rows, computes all 256 output cols.
// W1 (rearranged [k][n] with n<128 -> top half, n>=128 -> bottom half) lives
// in 128KB dynamic smem, tf32-rounded at staging time. A (Z rows) streams
// from global (L2-resident after first touch). tf32 WMMA, fp32 accumulate.
// ---------------------------------------------------------------------------
__global__ void __launch_bounds__(256, 1)
precompute_kernel(const float* __restrict__ z,
                  const float* __restrict__ W1,
                  int n_nodes)
{
    // Stage combined B: s_B[k*256 + n]
    for (int idx = threadIdx.x; idx < 128 * 256; idx += blockDim.x) {
        int k = idx >> 8;
        int n = idx & 255;
        float w = (n < 128) ? W1[k * 128 + n]
                            : W1[(128 + k) * 128 + (n - 128)];
        s_B[idx] = wmma::__float_to_tf32(w);
    }
    __syncthreads();

    int warpId = threadIdx.x >> 5;
    int m0     = blockIdx.x * 64 + (warpId & 3) * 16;   // 16-row M tile
    int n_half = (warpId >> 2) * 128;                   // 0 -> U, 128 -> V
    if (m0 >= n_nodes) return;                          // tail guard (N%16==0)

    wmma::fragment<wmma::accumulator, 16, 16, 8, float> acc[8];
    #pragma unroll
    for (int j = 0; j < 8; j++) wmma::fill_fragment(acc[j], 0.0f);

    const float* A = z + (size_t)m0 * HID;

    #pragma unroll
    for (int k0 = 0; k0 < 128; k0 += 8) {
        wmma::fragment<wmma::matrix_a, 16, 16, 8, wmma::precision::tf32,
                       wmma::row_major> a;
        wmma::load_matrix_sync(a, A + k0, HID);
        #pragma unroll
        for (int i = 0; i < a.num_elements; i++)
            a.x[i] = wmma::__float_to_tf32(a.x[i]);

        #pragma unroll
        for (int j = 0; j < 8; j++) {
            wmma::fragment<wmma::matrix_b, 16, 16, 8, wmma::precision::tf32,
                           wmma::row_major> b;
            wmma::load_matrix_sync(b, s_B + k0 * 256 + n_half + j * 16, 256);
            wmma::mma_sync(acc[j], a, b, acc[j]);
        }
    }

    float* out_base = (n_half == 0) ? g_U : g_V;
    #pragma unroll
    for (int j = 0; j < 8; j++)
        wmma::store_matrix_sync(out_base + (size_t)m0 * HID + j * 16,
                                acc[j], HID, wmma::mem_row_major);
}

// ---------------------------------------------------------------------------
// Edge kernel: one warp per edge (grid-stride). Lane l owns hidden dims
// [4l, 4l+4): float4 gathers from U[src], V[dst] (512B contiguous per row,
// perfectly coalesced across the warp), relu-dot with W2, butterfly reduce,
// sigmoid. W2/b1 lane-slices loaded once per warp before the loop.
// edge_index arrives as int32 (harness downcasts the reference's int64).
// ---------------------------------------------------------------------------
__global__ void __launch_bounds__(256)
edge_kernel(const int* __restrict__ ei,
            const float* __restrict__ b1,
            const float* __restrict__ W2,
            const float* __restrict__ b2,
            float* __restrict__ out,
            int E)
{
    const int lane   = threadIdx.x & 31;
    const int warp   = (blockIdx.x * blockDim.x + threadIdx.x) >> 5;
    const int nwarps = (gridDim.x * blockDim.x) >> 5;

    const float4 w2v = *(const float4*)(W2 + lane * 4);
    const float4 b1v = *(const float4*)(b1 + lane * 4);
    const float  b2v = __ldg(b2);

    for (int e = warp; e < E; e += nwarps) {
        int s = __ldg(ei + e);       // uniform per warp -> 1 request
        int d = __ldg(ei + E + e);

        const float4 u = *(const float4*)(g_U + (size_t)s * HID + lane * 4);
        const float4 v = *(const float4*)(g_V + (size_t)d * HID + lane * 4);

        float acc;
        acc  = w2v.x * fmaxf(u.x + v.x + b1v.x, 0.0f);
        acc += w2v.y * fmaxf(u.y + v.y + b1v.y, 0.0f);
        acc += w2v.z * fmaxf(u.z + v.z + b1v.z, 0.0f);
        acc += w2v.w * fmaxf(u.w + v.w + b1v.w, 0.0f);

        #pragma unroll
        for (int o = 16; o; o >>= 1)
            acc += __shfl_xor_sync(0xffffffffu, acc, o);

        if (lane == 0)
            out[e] = 1.0f / (1.0f + __expf(-(acc + b2v)));
    }
}

// ---------------------------------------------------------------------------
// inputs (metadata order): z f32[100000*128], edge_index i32[2*1000000],
//                          W1 f32[256*128], b1 f32[128], W2 f32[128], b2 f32[1]
// output: f32[1000000]
// ---------------------------------------------------------------------------
extern "C" void kernel_launch(void* const* d_in, const int* in_sizes, int n_in,
                              void* d_out, int out_size)
{
    (void)n_in; (void)out_size;
    const float* z  = (const float*)d_in[0];
    const int*   ei = (const int*)  d_in[1];
    const float* W1 = (const float*)d_in[2];
    const float* b1 = (const float*)d_in[3];
    const float* W2 = (const float*)d_in[4];
    const float* b2 = (const float*)d_in[5];

    const int n_nodes = in_sizes[0] / HID;
    const int E       = in_sizes[1] / 2;

    cudaFuncSetAttribute(precompute_kernel,
                         cudaFuncAttributeMaxDynamicSharedMemorySize, 131072);

    int mblocks = (n_nodes + 63) / 64;
    precompute_kernel<<<mblocks, 256, 131072>>>(z, W1, n_nodes);

    edge_kernel<<<2368, 256>>>(ei, b1, W2, b2, (float*)d_out, E);
}

// round 3
// speedup vs baseline: 1.5445x; 1.5445x over previous
#include <cuda_runtime.h>
#include <cuda_fp16.h>
#include <mma.h>

using namespace nvcuda;

#define MAX_NODES 100000
#define HID 128
#define LD 68   // padded smem row stride (floats)

// Precomputed per-node projections, fp16 (51.2 MB total -> L2-resident)
__device__ __half g_U[(size_t)MAX_NODES * HID];   // Z @ W1[0:128,:]
__device__ __half g_V[(size_t)MAX_NODES * HID];   // Z @ W1[128:256,:]

extern __shared__ float s_mem[];   // phase 1: B tile [128 k][64 n]; phase 2: fp32 staging [128 m][64 n]

// ---------------------------------------------------------------------------
// Precompute: grid (m_tiles, 4). Block = 128 rows x 64 cols (n-chunk).
// chunk 0,1 -> U cols [0:64),[64:128); chunk 2,3 -> V likewise.
// 34.8KB smem/CTA -> 4-6 CTAs/SM (vs 1 before). tf32 WMMA, fp32 accum,
// fp16 output via smem staging (reuses the B tile region).
// ---------------------------------------------------------------------------
__global__ void __launch_bounds__(256)
precompute_kernel(const float* __restrict__ z,
                  const float* __restrict__ W1,
                  int n_nodes)
{
    const int tid   = threadIdx.x;
    const int chunk = blockIdx.y;              // 0..3

    // Stage B chunk: s_mem[k*LD + c], global n = chunk*64 + c
    for (int idx = tid; idx < 128 * 64; idx += 256) {
        int k = idx >> 6;
        int c = idx & 63;
        int n = chunk * 64 + c;
        float w = (n < 128) ? W1[k * 128 + n]
                            : W1[(128 + k) * 128 + (n - 128)];
        s_mem[k * LD + c] = wmma::__float_to_tf32(w);
    }
    __syncthreads();

    const int warpId = tid >> 5;
    const int m0     = blockIdx.x * 128 + warpId * 16;   // 16-row warp tile

    wmma::fragment<wmma::accumulator, 16, 16, 8, float> acc[4];
    #pragma unroll
    for (int j = 0; j < 4; j++) wmma::fill_fragment(acc[j], 0.0f);

    if (m0 + 16 <= n_nodes) {                  // N%16==0, so tiles are full or absent
        const float* A = z + (size_t)m0 * HID;
        #pragma unroll
        for (int k0 = 0; k0 < 128; k0 += 8) {
            wmma::fragment<wmma::matrix_a, 16, 16, 8, wmma::precision::tf32,
                           wmma::row_major> a;
            wmma::load_matrix_sync(a, A + k0, HID);
            #pragma unroll
            for (int i = 0; i < a.num_elements; i++)
                a.x[i] = wmma::__float_to_tf32(a.x[i]);

            #pragma unroll
            for (int j = 0; j < 4; j++) {
                wmma::fragment<wmma::matrix_b, 16, 16, 8, wmma::precision::tf32,
                               wmma::row_major> b;
                wmma::load_matrix_sync(b, s_mem + k0 * LD + j * 16, LD);
                wmma::mma_sync(acc[j], a, b, acc[j]);
            }
        }
    }
    __syncthreads();   // all B reads done; smem becomes staging

    if (m0 + 16 <= n_nodes) {
        #pragma unroll
        for (int j = 0; j < 4; j++)
            wmma::store_matrix_sync(s_mem + warpId * 16 * LD + j * 16,
                                    acc[j], LD, wmma::mem_row_major);
    }
    __syncthreads();

    // Convert staging -> fp16, write 16B per thread-iter
    __half* outb = (chunk < 2) ? g_U : g_V;
    const int colbase = (chunk & 1) * 64;
    for (int idx = tid; idx < 128 * 8; idx += 256) {
        int r  = idx >> 3;
        int c0 = (idx & 7) * 8;
        int m  = blockIdx.x * 128 + r;
        if (m < n_nodes) {
            const float* src = s_mem + r * LD + c0;
            __half2 h[4];
            h[0] = __floats2half2_rn(src[0], src[1]);
            h[1] = __floats2half2_rn(src[2], src[3]);
            h[2] = __floats2half2_rn(src[4], src[5]);
            h[3] = __floats2half2_rn(src[6], src[7]);
            *(uint4*)(outb + (size_t)m * HID + colbase + c0) = *(uint4*)h;
        }
    }
}

// ---------------------------------------------------------------------------
// Edge kernel: warp per edge, 2 edges per iteration (MLP). Lane l owns hidden
// dims [4l,4l+4): 8B fp16 gathers (256B/row, coalesced), relu-dot with W2,
// butterfly reduce, sigmoid.
// ---------------------------------------------------------------------------
__device__ __forceinline__ float relu_dot(uint2 u, uint2 v,
                                          float4 b1v, float4 w2v)
{
    float2 uA = __half22float2(((const __half2*)&u)[0]);
    float2 uB = __half22float2(((const __half2*)&u)[1]);
    float2 vA = __half22float2(((const __half2*)&v)[0]);
    float2 vB = __half22float2(((const __half2*)&v)[1]);
    float acc;
    acc  = w2v.x * fmaxf(uA.x + vA.x + b1v.x, 0.0f);
    acc += w2v.y * fmaxf(uA.y + vA.y + b1v.y, 0.0f);
    acc += w2v.z * fmaxf(uB.x + vB.x + b1v.z, 0.0f);
    acc += w2v.w * fmaxf(uB.y + vB.y + b1v.w, 0.0f);
    return acc;
}

__global__ void __launch_bounds__(256)
edge_kernel(const int* __restrict__ ei,
            const float* __restrict__ b1,
            const float* __restrict__ W2,
            const float* __restrict__ b2,
            float* __restrict__ out,
            int E)
{
    const int lane   = threadIdx.x & 31;
    const int warp   = (blockIdx.x * blockDim.x + threadIdx.x) >> 5;
    const int nwarps = (gridDim.x * blockDim.x) >> 5;

    const float4 w2v = *(const float4*)(W2 + lane * 4);
    const float4 b1v = *(const float4*)(b1 + lane * 4);
    const float  b2v = __ldg(b2);

    const __half* Ub = g_U + lane * 4;
    const __half* Vb = g_V + lane * 4;

    for (int e = warp * 2; e < E; e += nwarps * 2) {
        const int  e1   = e + 1;
        const bool has2 = (e1 < E);

        int s0 = __ldg(ei + e);
        int d0 = __ldg(ei + E + e);
        int s1 = has2 ? __ldg(ei + e1)     : s0;
        int d1 = has2 ? __ldg(ei + E + e1) : d0;

        uint2 u0 = *(const uint2*)(Ub + (size_t)s0 * HID);
        uint2 v0 = *(const uint2*)(Vb + (size_t)d0 * HID);
        uint2 u1 = *(const uint2*)(Ub + (size_t)s1 * HID);
        uint2 v1 = *(const uint2*)(Vb + (size_t)d1 * HID);

        float a0 = relu_dot(u0, v0, b1v, w2v);
        float a1 = relu_dot(u1, v1, b1v, w2v);

        #pragma unroll
        for (int o = 16; o; o >>= 1) {
            a0 += __shfl_xor_sync(0xffffffffu, a0, o);
            a1 += __shfl_xor_sync(0xffffffffu, a1, o);
        }

        if (lane == 0) {
            out[e] = 1.0f / (1.0f + __expf(-(a0 + b2v)));
            if (has2) out[e1] = 1.0f / (1.0f + __expf(-(a1 + b2v)));
        }
    }
}

// ---------------------------------------------------------------------------
// inputs: z f32[100000*128], edge_index i32[2*1000000],
//         W1 f32[256*128], b1 f32[128], W2 f32[128], b2 f32[1]
// output: f32[1000000]
// ---------------------------------------------------------------------------
extern "C" void kernel_launch(void* const* d_in, const int* in_sizes, int n_in,
                              void* d_out, int out_size)
{
    (void)n_in; (void)out_size;
    const float* z  = (const float*)d_in[0];
    const int*   ei = (const int*)  d_in[1];
    const float* W1 = (const float*)d_in[2];
    const float* b1 = (const float*)d_in[3];
    const float* W2 = (const float*)d_in[4];
    const float* b2 = (const float*)d_in[5];

    const int n_nodes = in_sizes[0] / HID;
    const int E       = in_sizes[1] / 2;

    const int smem_bytes = 128 * LD * sizeof(float);   // 34,816 B
    dim3 pgrid((n_nodes + 127) / 128, 4);
    precompute_kernel<<<pgrid, 256, smem_bytes>>>(z, W1, n_nodes);

    edge_kernel<<<2368, 256>>>(ei, b1, W2, b2, (float*)d_out, E);
}

// round 4
// speedup vs baseline: 1.6171x; 1.0470x over previous
#include <cuda_runtime.h>
#include <cuda_fp16.h>
#include <mma.h>

using namespace nvcuda;

#define MAX_NODES 100000
#define HID 128
#define LDA 136   // smem fp16 row stride (halves), +8 pad
#define LDS 132   // smem fp32 staging stride (floats), +4 pad

// Precomputed per-node projections, fp16 (51.2 MB total -> L2-resident)
__device__ __half g_U[(size_t)MAX_NODES * HID];   // Z @ W1[0:128,:]
__device__ __half g_V[(size_t)MAX_NODES * HID];   // Z @ W1[128:256,:]

// ---------------------------------------------------------------------------
// Precompute: grid (2, m_tiles). blockIdx.x = chunk (0 -> U, 1 -> V) is the
// fast grid dim so both chunks of a Z tile run adjacently -> Z DRAM-read once.
// Block: 128 m x 128 n, 8 warps (4 m-tiles x 2 n-tiles of 32x64).
// A (Z tile) and B (W1 chunk) staged in smem as fp16; HMMA.16816 fp32-accum.
// ---------------------------------------------------------------------------
extern __shared__ char smem_raw[];

__global__ void __launch_bounds__(256)
precompute_kernel(const float* __restrict__ z,
                  const float* __restrict__ W1,
                  int n_nodes)
{
    __half* sA = (__half*)smem_raw;              // [128][LDA]
    __half* sB = sA + 128 * LDA;                 // [128][LDA]
    float*  sS = (float*)smem_raw;               // staging [128][LDS] (reuse)

    const int tid   = threadIdx.x;
    const int chunk = blockIdx.x;                // 0 -> U, 1 -> V
    const int m0    = blockIdx.y * 128;
    const int mrem  = n_nodes - m0;              // rows valid in this tile

    // Stage A: Z[m0:m0+128, :] fp32 -> fp16 (zero-pad tail rows)
    for (int idx = tid; idx < 128 * 32; idx += 256) {      // float4 granularity
        int r  = idx >> 5;
        int c4 = (idx & 31) << 2;
        __half2 h[2];
        if (r < mrem) {
            float4 f = *(const float4*)(z + (size_t)(m0 + r) * HID + c4);
            h[0] = __floats2half2_rn(f.x, f.y);
            h[1] = __floats2half2_rn(f.z, f.w);
        } else {
            h[0] = h[1] = __floats2half2_rn(0.f, 0.f);
        }
        *(uint2*)(sA + r * LDA + c4) = *(uint2*)h;
    }
    // Stage B: W1 rows [chunk*128 : chunk*128+128), [k][n] layout as stored
    const float* Wb = W1 + (size_t)chunk * 128 * HID;
    for (int idx = tid; idx < 128 * 32; idx += 256) {
        int r  = idx >> 5;
        int c4 = (idx & 31) << 2;
        float4 f = *(const float4*)(Wb + (size_t)r * HID + c4);
        __half2 h[2];
        h[0] = __floats2half2_rn(f.x, f.y);
        h[1] = __floats2half2_rn(f.z, f.w);
        *(uint2*)(sB + r * LDA + c4) = *(uint2*)h;
    }
    __syncthreads();

    const int warpId = tid >> 5;
    const int wm = warpId & 3;                   // m-tile: rows wm*32 .. +32
    const int wn = warpId >> 2;                  // n-tile: cols wn*64 .. +64

    wmma::fragment<wmma::accumulator, 16, 16, 16, float> acc[2][4];
    #pragma unroll
    for (int i = 0; i < 2; i++)
        #pragma unroll
        for (int j = 0; j < 4; j++)
            wmma::fill_fragment(acc[i][j], 0.0f);

    #pragma unroll
    for (int k0 = 0; k0 < 128; k0 += 16) {
        wmma::fragment<wmma::matrix_a, 16, 16, 16, __half, wmma::row_major> a[2];
        #pragma unroll
        for (int i = 0; i < 2; i++)
            wmma::load_matrix_sync(a[i], sA + (wm * 32 + i * 16) * LDA + k0, LDA);
        #pragma unroll
        for (int j = 0; j < 4; j++) {
            wmma::fragment<wmma::matrix_b, 16, 16, 16, __half, wmma::row_major> b;
            wmma::load_matrix_sync(b, sB + k0 * LDA + wn * 64 + j * 16, LDA);
            #pragma unroll
            for (int i = 0; i < 2; i++)
                wmma::mma_sync(acc[i][j], a[i], b, acc[i][j]);
        }
    }
    __syncthreads();   // smem becomes fp32 staging

    #pragma unroll
    for (int i = 0; i < 2; i++)
        #pragma unroll
        for (int j = 0; j < 4; j++)
            wmma::store_matrix_sync(sS + (wm * 32 + i * 16) * LDS + wn * 64 + j * 16,
                                    acc[i][j], LDS, wmma::mem_row_major);
    __syncthreads();

    // Convert staging -> fp16 output, 16B stores
    __half* outb = (chunk == 0) ? g_U : g_V;
    for (int idx = tid; idx < 128 * 16; idx += 256) {      // uint4 granularity
        int r  = idx >> 4;
        int c8 = (idx & 15) << 3;
        if (r < mrem) {
            const float* src = sS + r * LDS + c8;
            __half2 h[4];
            h[0] = __floats2half2_rn(src[0], src[1]);
            h[1] = __floats2half2_rn(src[2], src[3]);
            h[2] = __floats2half2_rn(src[4], src[5]);
            h[3] = __floats2half2_rn(src[6], src[7]);
            *(uint4*)(outb + (size_t)(m0 + r) * HID + c8) = *(uint4*)h;
        }
    }
}

// ---------------------------------------------------------------------------
// Edge kernel: 8 lanes per edge, 4 edges per warp. Lane group l8 owns hidden
// dims [l8*16, l8*16+16): two uint4 fp16 gathers per row (full 256B row per
// 8-lane group, coalesced). half2 add/add/max, fp32 dot with W2, 3-shfl
// reduce (serves 4 edges at once), sigmoid.
// ---------------------------------------------------------------------------
__global__ void __launch_bounds__(256)
edge_kernel(const int* __restrict__ ei,
            const float* __restrict__ b1,
            const float* __restrict__ W2,
            const float* __restrict__ b2,
            float* __restrict__ out,
            int E)
{
    const int lane = threadIdx.x & 31;
    const int sub  = lane >> 3;                  // edge slot 0..3 in warp
    const int l8   = lane & 7;                   // dim group
    const int gw   = (blockIdx.x * blockDim.x + threadIdx.x) >> 5;
    const int nw   = (gridDim.x * blockDim.x) >> 5;

    // Per-lane constants for dims [l8*16, l8*16+16)
    __half2 b1h[8];
    float   w2f[16];
    {
        const float* b1p = b1 + l8 * 16;
        const float* w2p = W2 + l8 * 16;
        #pragma unroll
        for (int j = 0; j < 8; j++)
            b1h[j] = __floats2half2_rn(b1p[2 * j], b1p[2 * j + 1]);
        #pragma unroll
        for (int j = 0; j < 16; j++)
            w2f[j] = w2p[j];
    }
    const float   b2v   = __ldg(b2);
    const __half2 zero2 = __floats2half2_rn(0.f, 0.f);

    const __half* Ub = g_U + l8 * 16;
    const __half* Vb = g_V + l8 * 16;

    for (int e4 = gw * 4; e4 < E; e4 += nw * 4) {
        const int  e     = e4 + sub;
        const bool valid = (e < E);

        int s = valid ? __ldg(ei + e)     : 0;
        int d = valid ? __ldg(ei + E + e) : 0;

        uint4 uraw[2], vraw[2];
        const uint4* up = (const uint4*)(Ub + (size_t)s * HID);
        const uint4* vp = (const uint4*)(Vb + (size_t)d * HID);
        uraw[0] = up[0]; uraw[1] = up[1];
        vraw[0] = vp[0]; vraw[1] = vp[1];

        const __half2* u2 = (const __half2*)uraw;
        const __half2* v2 = (const __half2*)vraw;

        float acc = 0.0f;
        #pragma unroll
        for (int j = 0; j < 8; j++) {
            __half2 t = __hmax2(__hadd2(__hadd2(u2[j], v2[j]), b1h[j]), zero2);
            float2  f = __half22float2(t);
            acc = fmaf(w2f[2 * j],     f.x, acc);
            acc = fmaf(w2f[2 * j + 1], f.y, acc);
        }

        // Reduce within each 8-lane group (all 4 edges in parallel)
        acc += __shfl_xor_sync(0xffffffffu, acc, 4);
        acc += __shfl_xor_sync(0xffffffffu, acc, 2);
        acc += __shfl_xor_sync(0xffffffffu, acc, 1);

        if (l8 == 0 && valid)
            out[e] = 1.0f / (1.0f + __expf(-(acc + b2v)));
    }
}

// ---------------------------------------------------------------------------
// inputs: z f32[100000*128], edge_index i32[2*1000000],
//         W1 f32[256*128], b1 f32[128], W2 f32[128], b2 f32[1]
// output: f32[1000000]
// ---------------------------------------------------------------------------
extern "C" void kernel_launch(void* const* d_in, const int* in_sizes, int n_in,
                              void* d_out, int out_size)
{
    (void)n_in; (void)out_size;
    const float* z  = (const float*)d_in[0];
    const int*   ei = (const int*)  d_in[1];
    const float* W1 = (const float*)d_in[2];
    const float* b1 = (const float*)d_in[3];
    const float* W2 = (const float*)d_in[4];
    const float* b2 = (const float*)d_in[5];

    const int n_nodes = in_sizes[0] / HID;
    const int E       = in_sizes[1] / 2;

    const int smem_bytes = 2 * 128 * LDA * sizeof(__half);   // 69,632 B
    static int configured = 0;
    cudaFuncSetAttribute(precompute_kernel,
                         cudaFuncAttributeMaxDynamicSharedMemorySize, smem_bytes);
    (void)configured;

    dim3 pgrid(2, (n_nodes + 127) / 128);
    precompute_kernel<<<pgrid, 256, smem_bytes>>>(z, W1, n_nodes);

    edge_kernel<<<2368, 256>>>(ei, b1, W2, b2, (float*)d_out, E);
}

// round 5
// speedup vs baseline: 2.4686x; 1.5265x over previous
#include <cuda_runtime.h>
#include <cuda_fp16.h>
#include <mma.h>

using namespace nvcuda;

#define MAX_NODES 100000
#define HID 128
#define LDA 136   // smem fp16 row stride (halves), +8 pad
#define LDS 132   // smem fp32 staging stride (floats), +4 pad

// Precomputed per-node projections, fp16 (51.2 MB total -> L2-resident)
__device__ __half g_U[(size_t)MAX_NODES * HID];   // Z @ W1[0:128,:]
__device__ __half g_V[(size_t)MAX_NODES * HID];   // Z @ W1[128:256,:]

extern __shared__ char smem_raw[];

// ---------------------------------------------------------------------------
// Precompute: grid (2, 1563). blockIdx.x = chunk (0 -> U, 1 -> V), fastest
// dim so the two chunks of a Z tile are co-scheduled (Z tile L2-hot).
// Block: 64 m x 128 n, 8 warps = 4 m-tiles x 2 n-halves, warp tile 16x64.
// smem 52.2KB -> 4 CTAs/SM (vs 3 at 69.6KB), 3126 blocks (vs 1564): shorter
// serial phases, finer waves. fp16 HMMA, fp32 accum, fp16 out via staging.
// ---------------------------------------------------------------------------
__global__ void __launch_bounds__(256)
precompute_kernel(const float* __restrict__ z,
                  const float* __restrict__ W1,
                  int n_nodes)
{
    __half* sA = (__half*)smem_raw;              // [64][LDA]
    __half* sB = sA + 64 * LDA;                  // [128][LDA]
    float*  sS = (float*)smem_raw;               // staging [64][LDS] (reuse)

    const int tid   = threadIdx.x;
    const int chunk = blockIdx.x;                // 0 -> U, 1 -> V
    const int m0    = blockIdx.y * 64;
    const int mrem  = n_nodes - m0;

    // Stage A: Z[m0:m0+64, :] fp32 -> fp16 (zero-pad tail rows)
    for (int idx = tid; idx < 64 * 32; idx += 256) {
        int r  = idx >> 5;
        int c4 = (idx & 31) << 2;
        __half2 h[2];
        if (r < mrem) {
            float4 f = *(const float4*)(z + (size_t)(m0 + r) * HID + c4);
            h[0] = __floats2half2_rn(f.x, f.y);
            h[1] = __floats2half2_rn(f.z, f.w);
        } else {
            h[0] = h[1] = __floats2half2_rn(0.f, 0.f);
        }
        *(uint2*)(sA + r * LDA + c4) = *(uint2*)h;
    }
    // Stage B: W1 rows [chunk*128, +128) (L2-resident, 128KB total)
    const float* Wb = W1 + (size_t)chunk * 128 * HID;
    for (int idx = tid; idx < 128 * 32; idx += 256) {
        int r  = idx >> 5;
        int c4 = (idx & 31) << 2;
        float4 f = *(const float4*)(Wb + (size_t)r * HID + c4);
        __half2 h[2];
        h[0] = __floats2half2_rn(f.x, f.y);
        h[1] = __floats2half2_rn(f.z, f.w);
        *(uint2*)(sB + r * LDA + c4) = *(uint2*)h;
    }
    __syncthreads();

    const int warpId = tid >> 5;
    const int wm = (warpId & 3) * 16;            // m offset in tile
    const int wn = (warpId >> 2) * 64;           // n offset

    wmma::fragment<wmma::accumulator, 16, 16, 16, float> acc[4];
    #pragma unroll
    for (int j = 0; j < 4; j++) wmma::fill_fragment(acc[j], 0.0f);

    #pragma unroll
    for (int k0 = 0; k0 < 128; k0 += 16) {
        wmma::fragment<wmma::matrix_a, 16, 16, 16, __half, wmma::row_major> a;
        wmma::load_matrix_sync(a, sA + wm * LDA + k0, LDA);
        #pragma unroll
        for (int j = 0; j < 4; j++) {
            wmma::fragment<wmma::matrix_b, 16, 16, 16, __half, wmma::row_major> b;
            wmma::load_matrix_sync(b, sB + k0 * LDA + wn + j * 16, LDA);
            wmma::mma_sync(acc[j], a, b, acc[j]);
        }
    }
    __syncthreads();   // B reads done; smem becomes staging

    #pragma unroll
    for (int j = 0; j < 4; j++)
        wmma::store_matrix_sync(sS + wm * LDS + wn + j * 16,
                                acc[j], LDS, wmma::mem_row_major);
    __syncthreads();

    // staging -> fp16, 16B stores
    __half* outb = (chunk == 0) ? g_U : g_V;
    for (int idx = tid; idx < 64 * 16; idx += 256) {
        int r  = idx >> 4;
        int c8 = (idx & 15) << 3;
        if (r < mrem) {
            const float* src = sS + r * LDS + c8;
            __half2 h[4];
            h[0] = __floats2half2_rn(src[0], src[1]);
            h[1] = __floats2half2_rn(src[2], src[3]);
            h[2] = __floats2half2_rn(src[4], src[5]);
            h[3] = __floats2half2_rn(src[6], src[7]);
            *(uint4*)(outb + (size_t)(m0 + r) * HID + c8) = *(uint4*)h;
        }
    }
}

// ---------------------------------------------------------------------------
// Edge kernel: 16 lanes per edge, 2 edges per warp. Lane group l16 owns dims
// [l16*8, l16*8+8): one uint4 fp16 gather per row (16 lanes x 16B = full
// 256B row, coalesced). Per-lane constants only 12 regs (vs 24 in R4) ->
// target occupancy ~75%. 4-shfl reduce serves both edges simultaneously.
// ---------------------------------------------------------------------------
__global__ void __launch_bounds__(256)
edge_kernel(const int* __restrict__ ei,
            const float* __restrict__ b1,
            const float* __restrict__ W2,
            const float* __restrict__ b2,
            float* __restrict__ out,
            int E)
{
    const int lane = threadIdx.x & 31;
    const int sub  = lane >> 4;                  // edge slot 0/1 in warp
    const int l16  = lane & 15;                  // dim group
    const int gw   = (blockIdx.x * blockDim.x + threadIdx.x) >> 5;
    const int nw   = (gridDim.x * blockDim.x) >> 5;

    // Constants for dims [l16*8, +8)
    __half2 b1h[4];
    float   w2f[8];
    {
        const float* b1p = b1 + l16 * 8;
        const float* w2p = W2 + l16 * 8;
        #pragma unroll
        for (int j = 0; j < 4; j++)
            b1h[j] = __floats2half2_rn(b1p[2 * j], b1p[2 * j + 1]);
        #pragma unroll
        for (int j = 0; j < 8; j++)
            w2f[j] = w2p[j];
    }
    const float   b2v   = __ldg(b2);
    const __half2 zero2 = __floats2half2_rn(0.f, 0.f);

    const __half* Ub = g_U + l16 * 8;
    const __half* Vb = g_V + l16 * 8;

    for (int e2 = gw * 2; e2 < E; e2 += nw * 2) {
        const int  e     = e2 + sub;
        const bool valid = (e < E);

        int s = valid ? __ldg(ei + e)     : 0;
        int d = valid ? __ldg(ei + E + e) : 0;

        uint4 uraw = *(const uint4*)(Ub + (size_t)s * HID);
        uint4 vraw = *(const uint4*)(Vb + (size_t)d * HID);

        const __half2* u2 = (const __half2*)&uraw;
        const __half2* v2 = (const __half2*)&vraw;

        float acc = 0.0f;
        #pragma unroll
        for (int j = 0; j < 4; j++) {
            __half2 t = __hmax2(__hadd2(__hadd2(u2[j], v2[j]), b1h[j]), zero2);
            float2  f = __half22float2(t);
            acc = fmaf(w2f[2 * j],     f.x, acc);
            acc = fmaf(w2f[2 * j + 1], f.y, acc);
        }

        // Reduce within each 16-lane group (both edges in parallel)
        acc += __shfl_xor_sync(0xffffffffu, acc, 8);
        acc += __shfl_xor_sync(0xffffffffu, acc, 4);
        acc += __shfl_xor_sync(0xffffffffu, acc, 2);
        acc += __shfl_xor_sync(0xffffffffu, acc, 1);

        if (l16 == 0 && valid)
            out[e] = 1.0f / (1.0f + __expf(-(acc + b2v)));
    }
}

// ---------------------------------------------------------------------------
// inputs: z f32[100000*128], edge_index i32[2*1000000],
//         W1 f32[256*128], b1 f32[128], W2 f32[128], b2 f32[1]
// output: f32[1000000]
// ---------------------------------------------------------------------------
extern "C" void kernel_launch(void* const* d_in, const int* in_sizes, int n_in,
                              void* d_out, int out_size)
{
    (void)n_in; (void)out_size;
    const float* z  = (const float*)d_in[0];
    const int*   ei = (const int*)  d_in[1];
    const float* W1 = (const float*)d_in[2];
    const float* b1 = (const float*)d_in[3];
    const float* W2 = (const float*)d_in[4];
    const float* b2 = (const float*)d_in[5];

    const int n_nodes = in_sizes[0] / HID;
    const int E       = in_sizes[1] / 2;

    const int smem_bytes = (64 + 128) * LDA * sizeof(__half);   // 52,224 B
    cudaFuncSetAttribute(precompute_kernel,
                         cudaFuncAttributeMaxDynamicSharedMemorySize, smem_bytes);

    dim3 pgrid(2, (n_nodes + 63) / 64);
    precompute_kernel<<<pgrid, 256, smem_bytes>>>(z, W1, n_nodes);

    edge_kernel<<<4440, 256>>>(ei, b1, W2, b2, (float*)d_out, E);
}

// round 6
// speedup vs baseline: 2.7908x; 1.1305x over previous
#include <cuda_runtime.h>
#include <cuda_fp16.h>
#include <mma.h>

using namespace nvcuda;

#define MAX_NODES 100000
#define HID 128
#define LDA 136   // smem fp16 row stride (halves), +8 pad
#define LDS 132   // smem fp32 staging stride (floats), +4 pad

// Precomputed per-node projections, fp16 (51.2 MB total -> L2-resident)
// g_U has b1 folded in: U = Z @ W1[0:128,:] + b1
__device__ __half g_U[(size_t)MAX_NODES * HID];
__device__ __half g_V[(size_t)MAX_NODES * HID];   // Z @ W1[128:256,:]

extern __shared__ char smem_raw[];

// ---------------------------------------------------------------------------
// Precompute: grid (2, 1563). blockIdx.x = chunk (0 -> U+b1, 1 -> V).
// Block: 64 m x 128 n, 8 warps = 4 m-tiles x 2 n-halves, warp tile 16x64.
// smem 52.2KB -> 4 CTAs/SM. fp16 HMMA, fp32 accum, fp16 out via staging.
// ---------------------------------------------------------------------------
__global__ void __launch_bounds__(256)
precompute_kernel(const float* __restrict__ z,
                  const float* __restrict__ W1,
                  const float* __restrict__ b1,
                  int n_nodes)
{
    __half* sA = (__half*)smem_raw;              // [64][LDA]
    __half* sB = sA + 64 * LDA;                  // [128][LDA]
    float*  sS = (float*)smem_raw;               // staging [64][LDS] (reuse)

    const int tid   = threadIdx.x;
    const int chunk = blockIdx.x;                // 0 -> U, 1 -> V
    const int m0    = blockIdx.y * 64;
    const int mrem  = n_nodes - m0;

    // Stage A: Z[m0:m0+64, :] fp32 -> fp16 (zero-pad tail rows)
    for (int idx = tid; idx < 64 * 32; idx += 256) {
        int r  = idx >> 5;
        int c4 = (idx & 31) << 2;
        __half2 h[2];
        if (r < mrem) {
            float4 f = *(const float4*)(z + (size_t)(m0 + r) * HID + c4);
            h[0] = __floats2half2_rn(f.x, f.y);
            h[1] = __floats2half2_rn(f.z, f.w);
        } else {
            h[0] = h[1] = __floats2half2_rn(0.f, 0.f);
        }
        *(uint2*)(sA + r * LDA + c4) = *(uint2*)h;
    }
    // Stage B: W1 rows [chunk*128, +128) (L2-resident)
    const float* Wb = W1 + (size_t)chunk * 128 * HID;
    for (int idx = tid; idx < 128 * 32; idx += 256) {
        int r  = idx >> 5;
        int c4 = (idx & 31) << 2;
        float4 f = *(const float4*)(Wb + (size_t)r * HID + c4);
        __half2 h[2];
        h[0] = __floats2half2_rn(f.x, f.y);
        h[1] = __floats2half2_rn(f.z, f.w);
        *(uint2*)(sB + r * LDA + c4) = *(uint2*)h;
    }
    __syncthreads();

    const int warpId = tid >> 5;
    const int wm = (warpId & 3) * 16;            // m offset in tile
    const int wn = (warpId >> 2) * 64;           // n offset

    wmma::fragment<wmma::accumulator, 16, 16, 16, float> acc[4];
    #pragma unroll
    for (int j = 0; j < 4; j++) wmma::fill_fragment(acc[j], 0.0f);

    #pragma unroll
    for (int k0 = 0; k0 < 128; k0 += 16) {
        wmma::fragment<wmma::matrix_a, 16, 16, 16, __half, wmma::row_major> a;
        wmma::load_matrix_sync(a, sA + wm * LDA + k0, LDA);
        #pragma unroll
        for (int j = 0; j < 4; j++) {
            wmma::fragment<wmma::matrix_b, 16, 16, 16, __half, wmma::row_major> b;
            wmma::load_matrix_sync(b, sB + k0 * LDA + wn + j * 16, LDA);
            wmma::mma_sync(acc[j], a, b, acc[j]);
        }
    }
    __syncthreads();   // B reads done; smem becomes staging

    #pragma unroll
    for (int j = 0; j < 4; j++)
        wmma::store_matrix_sync(sS + wm * LDS + wn + j * 16,
                                acc[j], LDS, wmma::mem_row_major);
    __syncthreads();

    // staging -> fp16 (chunk 0 folds b1), 16B stores
    __half* outb = (chunk == 0) ? g_U : g_V;
    for (int idx = tid; idx < 64 * 16; idx += 256) {
        int r  = idx >> 4;
        int c8 = (idx & 15) << 3;
        if (r < mrem) {
            const float* src = sS + r * LDS + c8;
            float f[8];
            #pragma unroll
            for (int t = 0; t < 8; t++) f[t] = src[t];
            if (chunk == 0) {
                float4 bA = *(const float4*)(b1 + c8);
                float4 bB = *(const float4*)(b1 + c8 + 4);
                f[0] += bA.x; f[1] += bA.y; f[2] += bA.z; f[3] += bA.w;
                f[4] += bB.x; f[5] += bB.y; f[6] += bB.z; f[7] += bB.w;
            }
            __half2 h[4];
            h[0] = __floats2half2_rn(f[0], f[1]);
            h[1] = __floats2half2_rn(f[2], f[3]);
            h[2] = __floats2half2_rn(f[4], f[5]);
            h[3] = __floats2half2_rn(f[6], f[7]);
            *(uint4*)(outb + (size_t)(m0 + r) * HID + c8) = *(uint4*)h;
        }
    }
}

// ---------------------------------------------------------------------------
// Edge kernel: 16 lanes per edge-slot, 2 slots per warp, 2 edges per slot
// per iteration (4 edges/warp/iter). b1 pre-folded into U, so per dim-pair:
// hadd2 + hmax2 + hfma2 (dot accumulated in half2, reduced in fp32).
// All 8 gathers issued before any math (MLP=8).
// ---------------------------------------------------------------------------
__global__ void __launch_bounds__(256)
edge_kernel(const int* __restrict__ ei,
            const float* __restrict__ W2,
            const float* __restrict__ b2,
            float* __restrict__ out,
            int E)
{
    const int lane = threadIdx.x & 31;
    const int sub  = lane >> 4;                  // slot 0/1
    const int l16  = lane & 15;                  // dim group
    const int gw   = (blockIdx.x * blockDim.x + threadIdx.x) >> 5;
    const int nw   = (gridDim.x * blockDim.x) >> 5;

    // W2 slice for dims [l16*8, +8) as half2
    __half2 w2h[4];
    {
        const float* w2p = W2 + l16 * 8;
        #pragma unroll
        for (int j = 0; j < 4; j++)
            w2h[j] = __floats2half2_rn(w2p[2 * j], w2p[2 * j + 1]);
    }
    const float   b2v   = __ldg(b2);
    const __half2 zero2 = __floats2half2_rn(0.f, 0.f);

    const __half* Ub = g_U + l16 * 8;
    const __half* Vb = g_V + l16 * 8;

    for (int e4 = gw * 4; e4 < E; e4 += nw * 4) {
        const int  eA = e4 + sub * 2;            // this slot's edges: eA, eA+1
        const int  eB = eA + 1;
        const bool vA = (eA < E);
        const bool vB = (eB < E);

        int s0 = vA ? __ldg(ei + eA)     : 0;
        int d0 = vA ? __ldg(ei + E + eA) : 0;
        int s1 = vB ? __ldg(ei + eB)     : 0;
        int d1 = vB ? __ldg(ei + E + eB) : 0;

        uint4 u0 = *(const uint4*)(Ub + (size_t)s0 * HID);
        uint4 v0 = *(const uint4*)(Vb + (size_t)d0 * HID);
        uint4 u1 = *(const uint4*)(Ub + (size_t)s1 * HID);
        uint4 v1 = *(const uint4*)(Vb + (size_t)d1 * HID);

        const __half2* u0h = (const __half2*)&u0;
        const __half2* v0h = (const __half2*)&v0;
        const __half2* u1h = (const __half2*)&u1;
        const __half2* v1h = (const __half2*)&v1;

        __half2 p0 = zero2, p1 = zero2;
        #pragma unroll
        for (int j = 0; j < 4; j++) {
            __half2 t0 = __hmax2(__hadd2(u0h[j], v0h[j]), zero2);
            __half2 t1 = __hmax2(__hadd2(u1h[j], v1h[j]), zero2);
            p0 = __hfma2(t0, w2h[j], p0);
            p1 = __hfma2(t1, w2h[j], p1);
        }

        float a0 = __low2float(p0) + __high2float(p0);
        float a1 = __low2float(p1) + __high2float(p1);

        // Reduce within each 16-lane group (slots independent)
        #pragma unroll
        for (int o = 8; o; o >>= 1) {
            a0 += __shfl_xor_sync(0xffffffffu, a0, o);
            a1 += __shfl_xor_sync(0xffffffffu, a1, o);
        }

        if (l16 == 0) {
            if (vA) out[eA] = 1.0f / (1.0f + __expf(-(a0 + b2v)));
            if (vB) out[eB] = 1.0f / (1.0f + __expf(-(a1 + b2v)));
        }
    }
}

// ---------------------------------------------------------------------------
// inputs: z f32[100000*128], edge_index i32[2*1000000],
//         W1 f32[256*128], b1 f32[128], W2 f32[128], b2 f32[1]
// output: f32[1000000]
// ---------------------------------------------------------------------------
extern "C" void kernel_launch(void* const* d_in, const int* in_sizes, int n_in,
                              void* d_out, int out_size)
{
    (void)n_in; (void)out_size;
    const float* z  = (const float*)d_in[0];
    const int*   ei = (const int*)  d_in[1];
    const float* W1 = (const float*)d_in[2];
    const float* b1 = (const float*)d_in[3];
    const float* W2 = (const float*)d_in[4];
    const float* b2 = (const float*)d_in[5];

    const int n_nodes = in_sizes[0] / HID;
    const int E       = in_sizes[1] / 2;

    const int smem_bytes = (64 + 128) * LDA * sizeof(__half);   // 52,224 B
    cudaFuncSetAttribute(precompute_kernel,
                         cudaFuncAttributeMaxDynamicSharedMemorySize, smem_bytes);

    dim3 pgrid(2, (n_nodes + 63) / 64);
    precompute_kernel<<<pgrid, 256, smem_bytes>>>(z, W1, b1, n_nodes);

    edge_kernel<<<4440, 256>>>(ei, W2, b2, (float*)d_out, E);
}

// round 7
// speedup vs baseline: 3.3255x; 1.1916x over previous
#include <cuda_runtime.h>
#include <cuda_fp16.h>
#include <mma.h>

using namespace nvcuda;

#define MAX_NODES 100000
#define HID 128
#define KEXT 144          // 128 Z dims + 1 bias row + 15 zero pad (k%16==0)
#define LDA2 152          // smem row stride (halves): 144+8 pad -> conflict-free ldmatrix
#define YTILES 522        // grid.y; each CTA handles 3 m-tiles (522*3=1566 >= 1563)

// Precomputed per-node projections, fp16 (51.2 MB total -> L2-resident)
// g_U = Z @ W1[0:128,:] + b1  (bias folded via K-extension row)
__device__ __half g_U[(size_t)MAX_NODES * HID];
__device__ __half g_V[(size_t)MAX_NODES * HID];   // Z @ W1[128:256,:]

// W1 pre-converted to fp16, extended layout: [chunk][KEXT][HID]
//   k <  128 : W1[chunk*128 + k][n]
//   k == 128 : b1[n] for chunk 0, 0 for chunk 1
//   k >  128 : 0
__device__ __half g_W1h[2 * KEXT * HID];

extern __shared__ char smem_raw[];

// ---------------------------------------------------------------------------
// One-shot W1/b1 -> fp16 extended conversion (36,864 elements).
// ---------------------------------------------------------------------------
__global__ void w1_convert_kernel(const float* __restrict__ W1,
                                  const float* __restrict__ b1)
{
    int i = blockIdx.x * 256 + threadIdx.x;
    if (i >= 2 * KEXT * HID) return;
    int n = i & (HID - 1);
    int k = (i >> 7) % KEXT;
    int c = i / (KEXT * HID);
    float v;
    if (k < 128)       v = W1[((size_t)c * 128 + k) * HID + n];
    else if (k == 128) v = (c == 0) ? b1[n] : 0.0f;
    else               v = 0.0f;
    g_W1h[i] = __float2half(v);
}

// ---------------------------------------------------------------------------
// Precompute: grid (2, YTILES). blockIdx.x = chunk (0 -> U+b1, 1 -> V).
// Each CTA stages its B (fp16, 144x128, plain 16B copies) ONCE, then loops
// 3 m-tiles: stage A (Z fp32->fp16, 1.0 bias column), 9 k-step HMMA,
// epilogue = f32 acc fragment -> f16 fragment -> store_matrix_sync direct
// to global (no fp32 smem staging, no extra syncs).
// ---------------------------------------------------------------------------
__global__ void __launch_bounds__(256)
precompute_kernel(const float* __restrict__ z, int n_nodes)
{
    __half* sA = (__half*)smem_raw;              // [64][LDA2]
    __half* sB = sA + 64 * LDA2;                 // [KEXT][LDA2]

    const int tid   = threadIdx.x;
    const int chunk = blockIdx.x;

    // Stage B once: g_W1h[chunk] -> sB (16B copies, no conversion)
    const __half* Wh = g_W1h + (size_t)chunk * KEXT * HID;
    for (int idx = tid; idx < KEXT * 16; idx += 256) {
        int r  = idx >> 4;
        int c8 = (idx & 15) << 3;
        *(uint4*)(sB + r * LDA2 + c8) = *(const uint4*)(Wh + r * HID + c8);
    }
    // A constant columns 128..143 (written once; constant across tiles):
    // col 128 = 1.0 (bias), 129..143 = 0
    for (int i = tid; i < 64 * 4; i += 256) {
        int r  = i >> 2;
        int c4 = 128 + (i & 3) * 4;
        __half h4[4];
        h4[0] = __float2half((c4 == 128) ? 1.0f : 0.0f);
        h4[1] = h4[2] = h4[3] = __float2half(0.0f);
        *(uint2*)(sA + r * LDA2 + c4) = *(uint2*)h4;
    }

    const int warpId = tid >> 5;
    const int wm = (warpId & 3) * 16;            // warp m offset in tile
    const int wn = (warpId >> 2) * 64;           // warp n offset
    __half* outb = (chunk == 0) ? g_U : g_V;

    #pragma unroll 1
    for (int t = 0; t < 3; t++) {
        const int tile = blockIdx.y + t * YTILES;
        const int m0   = tile * 64;
        const int mrem = n_nodes - m0;           // may be <=0 for overhang tiles

        __syncthreads();   // B ready (t=0) / previous MMA finished (t>0)

        // Stage A cols 0..127: Z fp32 -> fp16, zero-pad invalid rows
        for (int idx = tid; idx < 64 * 32; idx += 256) {
            int r  = idx >> 5;
            int c4 = (idx & 31) << 2;
            __half2 h[2];
            if (r < mrem) {
                float4 f = *(const float4*)(z + (size_t)(m0 + r) * HID + c4);
                h[0] = __floats2half2_rn(f.x, f.y);
                h[1] = __floats2half2_rn(f.z, f.w);
            } else {
                h[0] = h[1] = __floats2half2_rn(0.f, 0.f);
            }
            *(uint2*)(sA + r * LDA2 + c4) = *(uint2*)h;
        }
        __syncthreads();

        if (m0 + wm < n_nodes) {                 // whole warp-tile valid (n_nodes%16==0)
            wmma::fragment<wmma::accumulator, 16, 16, 16, float> acc[4];
            #pragma unroll
            for (int j = 0; j < 4; j++) wmma::fill_fragment(acc[j], 0.0f);

            #pragma unroll
            for (int k0 = 0; k0 < KEXT; k0 += 16) {
                wmma::fragment<wmma::matrix_a, 16, 16, 16, __half, wmma::row_major> a;
                wmma::load_matrix_sync(a, sA + wm * LDA2 + k0, LDA2);
                #pragma unroll
                for (int j = 0; j < 4; j++) {
                    wmma::fragment<wmma::matrix_b, 16, 16, 16, __half, wmma::row_major> b;
                    wmma::load_matrix_sync(b, sB + k0 * LDA2 + wn + j * 16, LDA2);
                    wmma::mma_sync(acc[j], a, b, acc[j]);
                }
            }

            // f32 acc -> f16 fragment, store straight to global (row-major, ld=128)
            #pragma unroll
            for (int j = 0; j < 4; j++) {
                wmma::fragment<wmma::accumulator, 16, 16, 16, __half> hacc;
                #pragma unroll
                for (int i = 0; i < hacc.num_elements; i++)
                    hacc.x[i] = __float2half(acc[j].x[i]);
                wmma::store_matrix_sync(outb + (size_t)(m0 + wm) * HID + wn + j * 16,
                                        hacc, HID, wmma::mem_row_major);
            }
        }
    }
}

// ---------------------------------------------------------------------------
// Edge kernel (unchanged from R6): 16 lanes per edge-slot, 2 slots per warp,
// 2 edges per slot per iter. b1 pre-folded into U: hadd2+hmax2+hfma2 per
// dim pair, half2 dot, fp32 5-shfl-pair reduce, sigmoid.
// ---------------------------------------------------------------------------
__global__ void __launch_bounds__(256)
edge_kernel(const int* __restrict__ ei,
            const float* __restrict__ W2,
            const float* __restrict__ b2,
            float* __restrict__ out,
            int E)
{
    const int lane = threadIdx.x & 31;
    const int sub  = lane >> 4;
    const int l16  = lane & 15;
    const int gw   = (blockIdx.x * blockDim.x + threadIdx.x) >> 5;
    const int nw   = (gridDim.x * blockDim.x) >> 5;

    __half2 w2h[4];
    {
        const float* w2p = W2 + l16 * 8;
        #pragma unroll
        for (int j = 0; j < 4; j++)
            w2h[j] = __floats2half2_rn(w2p[2 * j], w2p[2 * j + 1]);
    }
    const float   b2v   = __ldg(b2);
    const __half2 zero2 = __floats2half2_rn(0.f, 0.f);

    const __half* Ub = g_U + l16 * 8;
    const __half* Vb = g_V + l16 * 8;

    for (int e4 = gw * 4; e4 < E; e4 += nw * 4) {
        const int  eA = e4 + sub * 2;
        const int  eB = eA + 1;
        const bool vA = (eA < E);
        const bool vB = (eB < E);

        int s0 = vA ? __ldg(ei + eA)     : 0;
        int d0 = vA ? __ldg(ei + E + eA) : 0;
        int s1 = vB ? __ldg(ei + eB)     : 0;
        int d1 = vB ? __ldg(ei + E + eB) : 0;

        uint4 u0 = *(const uint4*)(Ub + (size_t)s0 * HID);
        uint4 v0 = *(const uint4*)(Vb + (size_t)d0 * HID);
        uint4 u1 = *(const uint4*)(Ub + (size_t)s1 * HID);
        uint4 v1 = *(const uint4*)(Vb + (size_t)d1 * HID);

        const __half2* u0h = (const __half2*)&u0;
        const __half2* v0h = (const __half2*)&v0;
        const __half2* u1h = (const __half2*)&u1;
        const __half2* v1h = (const __half2*)&v1;

        __half2 p0 = zero2, p1 = zero2;
        #pragma unroll
        for (int j = 0; j < 4; j++) {
            __half2 t0 = __hmax2(__hadd2(u0h[j], v0h[j]), zero2);
            __half2 t1 = __hmax2(__hadd2(u1h[j], v1h[j]), zero2);
            p0 = __hfma2(t0, w2h[j], p0);
            p1 = __hfma2(t1, w2h[j], p1);
        }

        float a0 = __low2float(p0) + __high2float(p0);
        float a1 = __low2float(p1) + __high2float(p1);

        #pragma unroll
        for (int o = 8; o; o >>= 1) {
            a0 += __shfl_xor_sync(0xffffffffu, a0, o);
            a1 += __shfl_xor_sync(0xffffffffu, a1, o);
        }

        if (l16 == 0) {
            if (vA) out[eA] = 1.0f / (1.0f + __expf(-(a0 + b2v)));
            if (vB) out[eB] = 1.0f / (1.0f + __expf(-(a1 + b2v)));
        }
    }
}

// ---------------------------------------------------------------------------
// inputs: z f32[100000*128], edge_index i32[2*1000000],
//         W1 f32[256*128], b1 f32[128], W2 f32[128], b2 f32[1]
// output: f32[1000000]
// ---------------------------------------------------------------------------
extern "C" void kernel_launch(void* const* d_in, const int* in_sizes, int n_in,
                              void* d_out, int out_size)
{
    (void)n_in; (void)out_size;
    const float* z  = (const float*)d_in[0];
    const int*   ei = (const int*)  d_in[1];
    const float* W1 = (const float*)d_in[2];
    const float* b1 = (const float*)d_in[3];
    const float* W2 = (const float*)d_in[4];
    const float* b2 = (const float*)d_in[5];

    const int n_nodes = in_sizes[0] / HID;
    const int E       = in_sizes[1] / 2;

    w1_convert_kernel<<<(2 * KEXT * HID + 255) / 256, 256>>>(W1, b1);

    const int smem_bytes = (64 + KEXT) * LDA2 * sizeof(__half);   // 63,232 B
    cudaFuncSetAttribute(precompute_kernel,
                         cudaFuncAttributeMaxDynamicSharedMemorySize, smem_bytes);

    dim3 pgrid(2, YTILES);
    precompute_kernel<<<pgrid, 256, smem_bytes>>>(z, n_nodes);

    edge_kernel<<<4440, 256>>>(ei, W2, b2, (float*)d_out, E);
}